// round 3
// baseline (speedup 1.0000x reference)
#include <cuda_runtime.h>

#define NB 1024
#define NR 512
#define ND 128
#define NO 64
#define BETA 6.5f
#define LAM_A 0.0033f
#define LAM_W 0.003f

// scratch (allocation-free rule: __device__ globals)
__device__ float g_s[NB * NR];
__device__ float g_h[NB * NR];
__device__ float g_coef[NB * NR];
__device__ float g_P[NB];

// ---------------------------------------------------------------------------
// K1: distances as GEMM.  q[b,r] = t0[b] + sum_d (-2 a z)[b,d]*c[r,d] + a[b,d]*c^2[r,d]
// 64x64 tile, 4x4 micro-tile, 256 threads.
// Epilogue: s = exp(-beta*sqrt(q)), h = -0.5*beta*s/sqrt(q).
// ---------------------------------------------------------------------------
#define K1_BM 64
#define K1_BN 64
#define K1_BK 16

__global__ __launch_bounds__(256) void k1_gemm(
    const float* __restrict__ z, const float* __restrict__ attn,
    const float* __restrict__ c)
{
    __shared__ float Au[K1_BK][K1_BM];   // -2*a*z
    __shared__ float Av[K1_BK][K1_BM];   // a
    __shared__ float Bc[K1_BK][K1_BN];   // c
    __shared__ float Bq[K1_BK][K1_BN];   // c^2
    __shared__ float t0s[K1_BM];

    int bm0 = blockIdx.x * K1_BM;   // batch tile
    int bn0 = blockIdx.y * K1_BN;   // rbf tile
    int tid = threadIdx.x;

    // t0[b] = sum_d a*z^2  (4 threads per row, quad shuffle reduce)
    {
        int row = tid >> 2, part = tid & 3;
        const float* zp = z + (bm0 + row) * ND + part * 32;
        const float* ap = attn + (bm0 + row) * ND + part * 32;
        float t = 0.f;
#pragma unroll 8
        for (int d0 = 0; d0 < 32; d0++) { float zz = zp[d0]; t = fmaf(ap[d0] * zz, zz, t); }
        t += __shfl_xor_sync(0xffffffffu, t, 1);
        t += __shfl_xor_sync(0xffffffffu, t, 2);
        if (part == 0) t0s[row] = t;
    }

    float acc[4][4] = {};
    int tm = tid >> 4, tn = tid & 15;

    for (int kc = 0; kc < ND; kc += K1_BK) {
        __syncthreads();
#pragma unroll
        for (int it = 0; it < 4; it++) {
            int i = tid + it * 256;
            int row = i >> 4, dcol = i & 15;
            float a  = attn[(bm0 + row) * ND + kc + dcol];
            float zz = z[(bm0 + row) * ND + kc + dcol];
            Au[dcol][row] = -2.f * a * zz;
            Av[dcol][row] = a;
            float cc = c[(bn0 + row) * ND + kc + dcol];
            Bc[dcol][row] = cc;
            Bq[dcol][row] = cc * cc;
        }
        __syncthreads();
#pragma unroll
        for (int kk = 0; kk < K1_BK; kk++) {
            float4 u = *(const float4*)&Au[kk][tm * 4];
            float4 v = *(const float4*)&Av[kk][tm * 4];
            float4 cc = *(const float4*)&Bc[kk][tn * 4];
            float4 qq = *(const float4*)&Bq[kk][tn * 4];
            float ui[4] = {u.x, u.y, u.z, u.w};
            float vi[4] = {v.x, v.y, v.z, v.w};
            float cj[4] = {cc.x, cc.y, cc.z, cc.w};
            float qj[4] = {qq.x, qq.y, qq.z, qq.w};
#pragma unroll
            for (int i = 0; i < 4; i++)
#pragma unroll
                for (int j = 0; j < 4; j++)
                    acc[i][j] = fmaf(ui[i], cj[j], fmaf(vi[i], qj[j], acc[i][j]));
        }
    }

#pragma unroll
    for (int i = 0; i < 4; i++) {
        int b = bm0 + tm * 4 + i;
        float t0 = t0s[tm * 4 + i];
        float4 so, ho;
        float* sp = &so.x; float* hp = &ho.x;
#pragma unroll
        for (int j = 0; j < 4; j++) {
            float q = fmaxf(acc[i][j] + t0, 1e-12f);
            float dd = sqrtf(q);
            float s = __expf(-BETA * dd);
            sp[j] = s;
            hp[j] = -0.5f * BETA * s / dd;
        }
        *(float4*)&g_s[b * NR + bn0 + tn * 4] = so;
        *(float4*)&g_h[b * NR + bn0 + tn * 4] = ho;
    }
}

// ---------------------------------------------------------------------------
// K23: one block per b.
// Phase 1 (float4): x[o] = sum_r s[r]*assoc[r,o], streamed from DRAM.
// gx = (2/O)*(x - teacher);  out_x = 2x.
// Phase A (float4, L2-hot re-read): coef[r] = h[r]*dot(gx, assoc[r,:]),
// new_assoc = assoc - lam_w*s[r]*gx;  P = sum_r coef.
// ---------------------------------------------------------------------------
__global__ __launch_bounds__(512) void k23(
    const float* __restrict__ assoc, const float* __restrict__ label,
    float* __restrict__ out_x, float* __restrict__ out_assoc)
{
    __shared__ float ss[NR];
    __shared__ float hh[NR];
    __shared__ __align__(16) float red[32][NO];
    __shared__ __align__(16) float gx[NO];
    __shared__ __align__(16) float coef[NR];

    int b = blockIdx.x;
    int tid = threadIdx.x;
    for (int i = tid; i < NR; i += 512) {
        ss[i] = g_s[b * NR + i];
        hh[i] = g_h[b * NR + i];
    }
    __syncthreads();

    const float* ab = assoc + (size_t)b * NR * NO;
    const float4* ab4 = (const float4*)ab;

    // Phase 1: 32 r-groups x 16 float4-columns
    {
        int o4 = tid & 15, rg = tid >> 4;
        float4 acc = make_float4(0.f, 0.f, 0.f, 0.f);
#pragma unroll
        for (int i = 0; i < NR / 32; i++) {
            int r = rg + 32 * i;
            float4 a = __ldg(ab4 + r * 16 + o4);
            float s = ss[r];
            acc.x = fmaf(s, a.x, acc.x);
            acc.y = fmaf(s, a.y, acc.y);
            acc.z = fmaf(s, a.z, acc.z);
            acc.w = fmaf(s, a.w, acc.w);
        }
        *(float4*)&red[rg][o4 * 4] = acc;
    }
    __syncthreads();
    if (tid < NO) {
        float x = 0.f;
#pragma unroll
        for (int g2 = 0; g2 < 32; g2++) x += red[g2][tid];
        float l = label[b * NO + tid];
        float tmin = fminf(-1.f, x);
        float teacher = tmin - l * tmin + l * fmaxf(1.f, x);
        out_x[b * NO + tid] = 2.f * x;                 // PHI = 2
        gx[tid] = 0.03125f * (x - teacher);            // (2/O)*(x - teacher)
    }
    __syncthreads();

    // Phase A: 8 lanes per r (16 float4 per row / 2 per lane? -> 8 lanes x 2 f4)
    // Use 8 lanes/row, each lane handles 2 float4 (o4 = sub, sub+8).
    {
        int sub = tid & 7;           // lane within row-group
        int rg  = tid >> 3;          // 64 row-groups
        const float4* gx4 = (const float4*)gx;
        float4 gA = gx4[sub];
        float4 gB = gx4[sub + 8];
        float4* ob4 = (float4*)(out_assoc + (size_t)b * NR * NO);
#pragma unroll
        for (int i = 0; i < NR / 64; i++) {
            int r = rg + 64 * i;
            float4 aA = __ldg(ab4 + r * 16 + sub);
            float4 aB = __ldg(ab4 + r * 16 + sub + 8);
            float p = aA.x * gA.x + aA.y * gA.y + aA.z * gA.z + aA.w * gA.w
                    + aB.x * gB.x + aB.y * gB.y + aB.z * gB.z + aB.w * gB.w;
            float f = LAM_W * ss[r];
            float4 oA, oB;
            oA.x = fmaf(-f, gA.x, aA.x); oA.y = fmaf(-f, gA.y, aA.y);
            oA.z = fmaf(-f, gA.z, aA.z); oA.w = fmaf(-f, gA.w, aA.w);
            oB.x = fmaf(-f, gB.x, aB.x); oB.y = fmaf(-f, gB.y, aB.y);
            oB.z = fmaf(-f, gB.z, aB.z); oB.w = fmaf(-f, gB.w, aB.w);
            ob4[r * 16 + sub] = oA;
            ob4[r * 16 + sub + 8] = oB;
            p += __shfl_xor_sync(0xffffffffu, p, 1);
            p += __shfl_xor_sync(0xffffffffu, p, 2);
            p += __shfl_xor_sync(0xffffffffu, p, 4);
            if (sub == 0) coef[r] = hh[r] * p;
        }
    }
    __syncthreads();

    if (tid < NR / 4)
        ((float4*)&g_coef[b * NR])[tid] = ((const float4*)coef)[tid];
    if (tid < 32) {
        float p = 0.f;
#pragma unroll
        for (int i = 0; i < 16; i++) p += coef[tid + 32 * i];
#pragma unroll
        for (int off = 16; off; off >>= 1)
            p += __shfl_xor_sync(0xffffffffu, p, off);
        if (tid == 0) g_P[b] = p;
    }
}

// ---------------------------------------------------------------------------
// K4: dual GEMM Q = coef @ C, S = coef @ C^2 (M=1024, N=128, K=512), full-K,
// fused epilogue: new_attn = max(attn - lam_a*(z^2*P - 2z*Q + S), 0)
// 64x16 tiles, 4x1 micro per GEMM, 256 threads -> 128 blocks.
// ---------------------------------------------------------------------------
#define K4_BM 64
#define K4_BN 16
#define K4_BK 16

__global__ __launch_bounds__(256) void k4_gemm(
    const float* __restrict__ c, const float* __restrict__ z,
    const float* __restrict__ attn, float* __restrict__ out_attn)
{
    __shared__ float Ac[K4_BK][K4_BM];
    __shared__ float Bc[K4_BK][K4_BN];
    __shared__ float Bq[K4_BK][K4_BN];

    int bm0 = blockIdx.x * K4_BM;   // b
    int bn0 = blockIdx.y * K4_BN;   // d
    int tid = threadIdx.x;
    int tm = tid >> 4, tn = tid & 15;

    float aq[4] = {};
    float as[4] = {};

    for (int kc = 0; kc < NR; kc += K4_BK) {
        __syncthreads();
#pragma unroll
        for (int it = 0; it < 4; it++) {
            int i = tid + it * 256;
            int row = i >> 4, col = i & 15;
            Ac[col][row] = g_coef[(bm0 + row) * NR + kc + col];
        }
        {
            int row = tid >> 4, col = tid & 15;
            float cc = c[(kc + row) * ND + bn0 + col];
            Bc[row][col] = cc;
            Bq[row][col] = cc * cc;
        }
        __syncthreads();
#pragma unroll
        for (int kk = 0; kk < K4_BK; kk++) {
            float4 a4 = *(const float4*)&Ac[kk][tm * 4];
            float bc = Bc[kk][tn];
            float bq = Bq[kk][tn];
            float ai[4] = {a4.x, a4.y, a4.z, a4.w};
#pragma unroll
            for (int i = 0; i < 4; i++) {
                aq[i] = fmaf(ai[i], bc, aq[i]);
                as[i] = fmaf(ai[i], bq, as[i]);
            }
        }
    }

    int k = bn0 + tn;
#pragma unroll
    for (int i = 0; i < 4; i++) {
        int b = bm0 + tm * 4 + i;
        float zz = z[b * ND + k];
        float P = g_P[b];
        float grad = fmaf(zz * zz, P, fmaf(-2.f * zz, aq[i], as[i]));
        out_attn[b * ND + k] = fmaxf(fmaf(-LAM_A, grad, attn[b * ND + k]), 0.f);
    }
}

// ---------------------------------------------------------------------------
extern "C" void kernel_launch(void* const* d_in, const int* in_sizes, int n_in,
                              void* d_out, int out_size)
{
    const float* z     = (const float*)d_in[0];  // (B,D)
    const float* label = (const float*)d_in[1];  // (B,O)
    const float* attn  = (const float*)d_in[2];  // (B,D)
    const float* assoc = (const float*)d_in[3];  // (B,R,O)
    const float* c     = (const float*)d_in[4];  // (R,D)

    float* out       = (float*)d_out;
    float* out_x     = out;                       // (B,O)
    float* out_attn  = out + NB * NO;             // (B,D)
    float* out_assoc = out + NB * NO + NB * ND;   // (B,R,O)

    k1_gemm<<<dim3(NB / K1_BM, NR / K1_BN), 256>>>(z, attn, c);
    k23<<<NB, 512>>>(assoc, label, out_x, out_assoc);
    k4_gemm<<<dim3(NB / K4_BM, ND / K4_BN), 256>>>(c, z, attn, out_attn);
}

// round 8
// speedup vs baseline: 1.3731x; 1.3731x over previous
#include <cuda_runtime.h>

#define NB 1024
#define NR 512
#define ND 128
#define NO 64
#define BETA 6.5f
#define LAM_A 0.0033f
#define LAM_W 0.003f

// scratch (allocation-free rule: __device__ globals)
__device__ float g_t0[NB];
__device__ float g_qp[2 * NB * NR];     // k1 split-D partials
__device__ float g_s[NB * NR];
__device__ float g_h[NB * NR];
__device__ float g_coef[NB * NR];
__device__ float g_P[NB];
__device__ float g_Qp[4 * NB * ND];     // k4 split-R partials
__device__ float g_Sp[4 * NB * ND];

// ---------------------------------------------------------------------------
// K0: t0[b] = sum_d attn*z^2   (one warp per b)
// ---------------------------------------------------------------------------
__global__ __launch_bounds__(256) void k0_t0(
    const float* __restrict__ z, const float* __restrict__ attn)
{
    int w = threadIdx.x >> 5, lane = threadIdx.x & 31;
    int b = blockIdx.x * 8 + w;
    float4 zz = *(const float4*)&z[b * ND + lane * 4];
    float4 a  = *(const float4*)&attn[b * ND + lane * 4];
    float t = a.x * zz.x * zz.x + a.y * zz.y * zz.y
            + a.z * zz.z * zz.z + a.w * zz.w * zz.w;
#pragma unroll
    for (int off = 16; off; off >>= 1)
        t += __shfl_xor_sync(0xffffffffu, t, off);
    if (lane == 0) g_t0[b] = t;
}

// ---------------------------------------------------------------------------
// K1: partial q[b,r] = sum_{d in half} (-2az)*c + a*c^2
// 64x64 tile, split-D(2), whole tile resident in smem (no k-reload/syncs).
// grid (16, 8, 2) = 256 blocks, 256 threads, 3 CTAs/SM.
// ---------------------------------------------------------------------------
#define K1_PAD 68
#define K1_SMEM_BYTES (4 * 64 * K1_PAD * 4)   // 69632

__global__ __launch_bounds__(256, 3) void k1_gemm(
    const float* __restrict__ z, const float* __restrict__ attn,
    const float* __restrict__ c)
{
    extern __shared__ __align__(16) float sm[];
    float* Au = sm;                    // [d][m] -2*a*z
    float* Av = Au + 64 * K1_PAD;      // [d][m] a
    float* Bc = Av + 64 * K1_PAD;      // [d][n] c
    float* Bq = Bc + 64 * K1_PAD;      // [d][n] c^2

    int bm0 = blockIdx.x * 64;         // batch tile
    int bn0 = blockIdx.y * 64;         // rbf tile
    int d0  = blockIdx.z * 64;         // d half
    int tid = threadIdx.x;

    // Load entire tiles once (transposed store; one-time conflicts OK)
#pragma unroll
    for (int it = 0; it < 4; it++) {
        int i = tid + it * 256;
        int row = i >> 4, c4 = (i & 15) * 4;
        float4 a  = *(const float4*)&attn[(bm0 + row) * ND + d0 + c4];
        float4 zz = *(const float4*)&z[(bm0 + row) * ND + d0 + c4];
        Au[(c4 + 0) * K1_PAD + row] = -2.f * a.x * zz.x;
        Au[(c4 + 1) * K1_PAD + row] = -2.f * a.y * zz.y;
        Au[(c4 + 2) * K1_PAD + row] = -2.f * a.z * zz.z;
        Au[(c4 + 3) * K1_PAD + row] = -2.f * a.w * zz.w;
        Av[(c4 + 0) * K1_PAD + row] = a.x;
        Av[(c4 + 1) * K1_PAD + row] = a.y;
        Av[(c4 + 2) * K1_PAD + row] = a.z;
        Av[(c4 + 3) * K1_PAD + row] = a.w;
        float4 cc = *(const float4*)&c[(bn0 + row) * ND + d0 + c4];
        Bc[(c4 + 0) * K1_PAD + row] = cc.x;
        Bc[(c4 + 1) * K1_PAD + row] = cc.y;
        Bc[(c4 + 2) * K1_PAD + row] = cc.z;
        Bc[(c4 + 3) * K1_PAD + row] = cc.w;
        Bq[(c4 + 0) * K1_PAD + row] = cc.x * cc.x;
        Bq[(c4 + 1) * K1_PAD + row] = cc.y * cc.y;
        Bq[(c4 + 2) * K1_PAD + row] = cc.z * cc.z;
        Bq[(c4 + 3) * K1_PAD + row] = cc.w * cc.w;
    }
    __syncthreads();

    int tm = tid >> 4, tn = tid & 15;
    float acc[4][4] = {};

#pragma unroll 8
    for (int kk = 0; kk < 64; kk++) {
        float4 u = *(const float4*)&Au[kk * K1_PAD + tm * 4];
        float4 v = *(const float4*)&Av[kk * K1_PAD + tm * 4];
        float4 bc = *(const float4*)&Bc[kk * K1_PAD + tn * 4];
        float4 bq = *(const float4*)&Bq[kk * K1_PAD + tn * 4];
        float ui[4] = {u.x, u.y, u.z, u.w};
        float vi[4] = {v.x, v.y, v.z, v.w};
        float cj[4] = {bc.x, bc.y, bc.z, bc.w};
        float qj[4] = {bq.x, bq.y, bq.z, bq.w};
#pragma unroll
        for (int i = 0; i < 4; i++)
#pragma unroll
            for (int j = 0; j < 4; j++)
                acc[i][j] = fmaf(ui[i], cj[j], fmaf(vi[i], qj[j], acc[i][j]));
    }

    float* qp = g_qp + (size_t)blockIdx.z * NB * NR;
#pragma unroll
    for (int i = 0; i < 4; i++) {
        float4 o = make_float4(acc[i][0], acc[i][1], acc[i][2], acc[i][3]);
        *(float4*)&qp[(bm0 + tm * 4 + i) * NR + bn0 + tn * 4] = o;
    }
}

// ---------------------------------------------------------------------------
// K1E: q = qp0+qp1+t0 -> s, h
// ---------------------------------------------------------------------------
__global__ __launch_bounds__(256) void k1e(void)
{
    int idx = blockIdx.x * 256 + threadIdx.x;
    float q = g_qp[idx] + g_qp[NB * NR + idx] + g_t0[idx >> 9];
    q = fmaxf(q, 1e-12f);
    float dd = sqrtf(q);
    float s = __expf(-BETA * dd);
    g_s[idx] = s;
    g_h[idx] = -0.5f * BETA * s / dd;
}

// ---------------------------------------------------------------------------
// K23: one block per b (unchanged from R3 — near DRAM floor).
// ---------------------------------------------------------------------------
__global__ __launch_bounds__(512) void k23(
    const float* __restrict__ assoc, const float* __restrict__ label,
    float* __restrict__ out_x, float* __restrict__ out_assoc)
{
    __shared__ float ss[NR];
    __shared__ float hh[NR];
    __shared__ __align__(16) float red[32][NO];
    __shared__ __align__(16) float gx[NO];
    __shared__ __align__(16) float coef[NR];

    int b = blockIdx.x;
    int tid = threadIdx.x;
    for (int i = tid; i < NR; i += 512) {
        ss[i] = g_s[b * NR + i];
        hh[i] = g_h[b * NR + i];
    }
    __syncthreads();

    const float* ab = assoc + (size_t)b * NR * NO;
    const float4* ab4 = (const float4*)ab;

    // Phase 1: 32 r-groups x 16 float4-columns
    {
        int o4 = tid & 15, rg = tid >> 4;
        float4 acc = make_float4(0.f, 0.f, 0.f, 0.f);
#pragma unroll
        for (int i = 0; i < NR / 32; i++) {
            int r = rg + 32 * i;
            float4 a = __ldg(ab4 + r * 16 + o4);
            float s = ss[r];
            acc.x = fmaf(s, a.x, acc.x);
            acc.y = fmaf(s, a.y, acc.y);
            acc.z = fmaf(s, a.z, acc.z);
            acc.w = fmaf(s, a.w, acc.w);
        }
        *(float4*)&red[rg][o4 * 4] = acc;
    }
    __syncthreads();
    if (tid < NO) {
        float x = 0.f;
#pragma unroll
        for (int g2 = 0; g2 < 32; g2++) x += red[g2][tid];
        float l = label[b * NO + tid];
        float tmin = fminf(-1.f, x);
        float teacher = tmin - l * tmin + l * fmaxf(1.f, x);
        out_x[b * NO + tid] = 2.f * x;                 // PHI = 2
        gx[tid] = 0.03125f * (x - teacher);            // (2/O)*(x - teacher)
    }
    __syncthreads();

    // Phase A: 8 lanes per r, float4; L2-hot re-read
    {
        int sub = tid & 7;
        int rg  = tid >> 3;
        const float4* gx4 = (const float4*)gx;
        float4 gA = gx4[sub];
        float4 gB = gx4[sub + 8];
        float4* ob4 = (float4*)(out_assoc + (size_t)b * NR * NO);
#pragma unroll
        for (int i = 0; i < NR / 64; i++) {
            int r = rg + 64 * i;
            float4 aA = __ldg(ab4 + r * 16 + sub);
            float4 aB = __ldg(ab4 + r * 16 + sub + 8);
            float p = aA.x * gA.x + aA.y * gA.y + aA.z * gA.z + aA.w * gA.w
                    + aB.x * gB.x + aB.y * gB.y + aB.z * gB.z + aB.w * gB.w;
            float f = LAM_W * ss[r];
            float4 oA, oB;
            oA.x = fmaf(-f, gA.x, aA.x); oA.y = fmaf(-f, gA.y, aA.y);
            oA.z = fmaf(-f, gA.z, aA.z); oA.w = fmaf(-f, gA.w, aA.w);
            oB.x = fmaf(-f, gB.x, aB.x); oB.y = fmaf(-f, gB.y, aB.y);
            oB.z = fmaf(-f, gB.z, aB.z); oB.w = fmaf(-f, gB.w, aB.w);
            ob4[r * 16 + sub] = oA;
            ob4[r * 16 + sub + 8] = oB;
            p += __shfl_xor_sync(0xffffffffu, p, 1);
            p += __shfl_xor_sync(0xffffffffu, p, 2);
            p += __shfl_xor_sync(0xffffffffu, p, 4);
            if (sub == 0) coef[r] = hh[r] * p;
        }
    }
    __syncthreads();

    if (tid < NR / 4)
        ((float4*)&g_coef[b * NR])[tid] = ((const float4*)coef)[tid];
    if (tid < 32) {
        float p = 0.f;
#pragma unroll
        for (int i = 0; i < 16; i++) p += coef[tid + 32 * i];
#pragma unroll
        for (int off = 16; off; off >>= 1)
            p += __shfl_xor_sync(0xffffffffu, p, off);
        if (tid == 0) g_P[b] = p;
    }
}

// ---------------------------------------------------------------------------
// K4: dual GEMM partials  Q = coef @ C, S = coef @ C^2
// M=1024(b), N=128(d), K=512(r), split-R(4). 64x32 tile, 4x2x2 micro.
// grid (16, 4, 4) = 256 blocks, 256 threads, whole tile in smem.
// ---------------------------------------------------------------------------
#define K4_PAD 68
#define K4_SMEM_BYTES ((128 * K4_PAD + 2 * 128 * 32) * 4)   // 67584

__global__ __launch_bounds__(256, 3) void k4_gemm(const float* __restrict__ c)
{
    extern __shared__ __align__(16) float sm4[];
    float* Ac = sm4;                   // [r][m] coef
    float* Bc = Ac + 128 * K4_PAD;     // [r][n] c
    float* Bq = Bc + 128 * 32;         // [r][n] c^2

    int bm0 = blockIdx.x * 64;
    int bn0 = blockIdx.y * 32;
    int r0  = blockIdx.z * 128;
    int tid = threadIdx.x;

    // Ac: 64 b-rows x 128 r (transposed store)
#pragma unroll
    for (int it = 0; it < 8; it++) {
        int i = tid + it * 256;
        int row = i >> 5, c4 = (i & 31) * 4;
        float4 a = *(const float4*)&g_coef[(bm0 + row) * NR + r0 + c4];
        Ac[(c4 + 0) * K4_PAD + row] = a.x;
        Ac[(c4 + 1) * K4_PAD + row] = a.y;
        Ac[(c4 + 2) * K4_PAD + row] = a.z;
        Ac[(c4 + 3) * K4_PAD + row] = a.w;
    }
    // B: 128 r-rows x 32 d (natural layout, coalesced both ways)
#pragma unroll
    for (int it = 0; it < 4; it++) {
        int i = tid + it * 256;
        int row = i >> 3, c4 = (i & 7) * 4;
        float4 cc = *(const float4*)&c[(r0 + row) * ND + bn0 + c4];
        *(float4*)&Bc[row * 32 + c4] = cc;
        float4 q2 = make_float4(cc.x * cc.x, cc.y * cc.y, cc.z * cc.z, cc.w * cc.w);
        *(float4*)&Bq[row * 32 + c4] = q2;
    }
    __syncthreads();

    int tm = tid >> 4, tn = tid & 15;
    float aq[4][2] = {};
    float as_[4][2] = {};

#pragma unroll 8
    for (int kk = 0; kk < 128; kk++) {
        float4 a4 = *(const float4*)&Ac[kk * K4_PAD + tm * 4];
        float2 bc = *(const float2*)&Bc[kk * 32 + tn * 2];
        float2 bq = *(const float2*)&Bq[kk * 32 + tn * 2];
        float ai[4] = {a4.x, a4.y, a4.z, a4.w};
#pragma unroll
        for (int i = 0; i < 4; i++) {
            aq[i][0] = fmaf(ai[i], bc.x, aq[i][0]);
            aq[i][1] = fmaf(ai[i], bc.y, aq[i][1]);
            as_[i][0] = fmaf(ai[i], bq.x, as_[i][0]);
            as_[i][1] = fmaf(ai[i], bq.y, as_[i][1]);
        }
    }

    float* Qp = g_Qp + (size_t)blockIdx.z * NB * ND;
    float* Sp = g_Sp + (size_t)blockIdx.z * NB * ND;
#pragma unroll
    for (int i = 0; i < 4; i++) {
        int b = bm0 + tm * 4 + i;
        int k = bn0 + tn * 2;
        *(float2*)&Qp[b * ND + k] = make_float2(aq[i][0], aq[i][1]);
        *(float2*)&Sp[b * ND + k] = make_float2(as_[i][0], as_[i][1]);
    }
}

// ---------------------------------------------------------------------------
// K5: merge partials + new_attn = max(attn - lam_a*(z^2*P - 2z*Q + S), 0)
// ---------------------------------------------------------------------------
__global__ __launch_bounds__(256) void k5_attn(
    const float* __restrict__ z, const float* __restrict__ attn,
    float* __restrict__ out_attn)
{
    int idx = blockIdx.x * 256 + threadIdx.x;
    int b = idx >> 7;
    float Q = g_Qp[idx] + g_Qp[NB * ND + idx]
            + g_Qp[2 * NB * ND + idx] + g_Qp[3 * NB * ND + idx];
    float S = g_Sp[idx] + g_Sp[NB * ND + idx]
            + g_Sp[2 * NB * ND + idx] + g_Sp[3 * NB * ND + idx];
    float zz = z[idx];
    float P = g_P[b];
    float grad = fmaf(zz * zz, P, fmaf(-2.f * zz, Q, S));
    out_attn[idx] = fmaxf(fmaf(-LAM_A, grad, attn[idx]), 0.f);
}

// ---------------------------------------------------------------------------
extern "C" void kernel_launch(void* const* d_in, const int* in_sizes, int n_in,
                              void* d_out, int out_size)
{
    const float* z     = (const float*)d_in[0];  // (B,D)
    const float* label = (const float*)d_in[1];  // (B,O)
    const float* attn  = (const float*)d_in[2];  // (B,D)
    const float* assoc = (const float*)d_in[3];  // (B,R,O)
    const float* c     = (const float*)d_in[4];  // (R,D)

    float* out       = (float*)d_out;
    float* out_x     = out;                       // (B,O)
    float* out_attn  = out + NB * NO;             // (B,D)
    float* out_assoc = out + NB * NO + NB * ND;   // (B,R,O)

    static bool attr_done = false;
    if (!attr_done) {
        cudaFuncSetAttribute(k1_gemm, cudaFuncAttributeMaxDynamicSharedMemorySize,
                             K1_SMEM_BYTES);
        cudaFuncSetAttribute(k4_gemm, cudaFuncAttributeMaxDynamicSharedMemorySize,
                             K4_SMEM_BYTES);
        attr_done = true;
    }

    k0_t0<<<NB / 8, 256>>>(z, attn);
    k1_gemm<<<dim3(NB / 64, NR / 64, 2), 256, K1_SMEM_BYTES>>>(z, attn, c);
    k1e<<<NB * NR / 256, 256>>>();
    k23<<<NB, 512>>>(assoc, label, out_x, out_assoc);
    k4_gemm<<<dim3(NB / 64, ND / 32, 4), 256, K4_SMEM_BYTES>>>(c);
    k5_attn<<<NB * ND / 256, 256>>>(z, attn, out_attn);
}

// round 11
// speedup vs baseline: 1.4394x; 1.0483x over previous
#include <cuda_runtime.h>

#define NB 1024
#define NR 512
#define ND 128
#define NO 64
#define BETA 6.5f
#define LAM_A 0.0033f
#define LAM_W 0.003f

// scratch (allocation-free rule: __device__ globals)
__device__ float g_qp[2 * NB * NR];     // k1 split-D partials
__device__ float g_coef[NB * NR];
__device__ float g_P[NB];
__device__ float g_Qp[4 * NB * ND];     // k4 split-R partials
__device__ float g_Sp[4 * NB * ND];

// ---------------------------------------------------------------------------
// K1: partial q[b,r] = sum_{d in half} (-2az)*c + a*c^2
// 64x64 tile, split-D(2), whole tile resident in smem.
// grid (16, 8, 2) = 256 blocks, 256 threads, 3 CTAs/SM.
// ---------------------------------------------------------------------------
#define K1_PAD 68
#define K1_SMEM_BYTES (4 * 64 * K1_PAD * 4)   // 69632

__global__ __launch_bounds__(256, 3) void k1_gemm(
    const float* __restrict__ z, const float* __restrict__ attn,
    const float* __restrict__ c)
{
    extern __shared__ __align__(16) float sm[];
    float* Au = sm;                    // [d][m] -2*a*z
    float* Av = Au + 64 * K1_PAD;      // [d][m] a
    float* Bc = Av + 64 * K1_PAD;      // [d][n] c
    float* Bq = Bc + 64 * K1_PAD;      // [d][n] c^2

    int bm0 = blockIdx.x * 64;
    int bn0 = blockIdx.y * 64;
    int d0  = blockIdx.z * 64;
    int tid = threadIdx.x;

#pragma unroll
    for (int it = 0; it < 4; it++) {
        int i = tid + it * 256;
        int row = i >> 4, c4 = (i & 15) * 4;
        float4 a  = *(const float4*)&attn[(bm0 + row) * ND + d0 + c4];
        float4 zz = *(const float4*)&z[(bm0 + row) * ND + d0 + c4];
        Au[(c4 + 0) * K1_PAD + row] = -2.f * a.x * zz.x;
        Au[(c4 + 1) * K1_PAD + row] = -2.f * a.y * zz.y;
        Au[(c4 + 2) * K1_PAD + row] = -2.f * a.z * zz.z;
        Au[(c4 + 3) * K1_PAD + row] = -2.f * a.w * zz.w;
        Av[(c4 + 0) * K1_PAD + row] = a.x;
        Av[(c4 + 1) * K1_PAD + row] = a.y;
        Av[(c4 + 2) * K1_PAD + row] = a.z;
        Av[(c4 + 3) * K1_PAD + row] = a.w;
        float4 cc = *(const float4*)&c[(bn0 + row) * ND + d0 + c4];
        Bc[(c4 + 0) * K1_PAD + row] = cc.x;
        Bc[(c4 + 1) * K1_PAD + row] = cc.y;
        Bc[(c4 + 2) * K1_PAD + row] = cc.z;
        Bc[(c4 + 3) * K1_PAD + row] = cc.w;
        Bq[(c4 + 0) * K1_PAD + row] = cc.x * cc.x;
        Bq[(c4 + 1) * K1_PAD + row] = cc.y * cc.y;
        Bq[(c4 + 2) * K1_PAD + row] = cc.z * cc.z;
        Bq[(c4 + 3) * K1_PAD + row] = cc.w * cc.w;
    }
    __syncthreads();

    int tm = tid >> 4, tn = tid & 15;
    float acc[4][4] = {};

#pragma unroll 8
    for (int kk = 0; kk < 64; kk++) {
        float4 u = *(const float4*)&Au[kk * K1_PAD + tm * 4];
        float4 v = *(const float4*)&Av[kk * K1_PAD + tm * 4];
        float4 bc = *(const float4*)&Bc[kk * K1_PAD + tn * 4];
        float4 bq = *(const float4*)&Bq[kk * K1_PAD + tn * 4];
        float ui[4] = {u.x, u.y, u.z, u.w};
        float vi[4] = {v.x, v.y, v.z, v.w};
        float cj[4] = {bc.x, bc.y, bc.z, bc.w};
        float qj[4] = {bq.x, bq.y, bq.z, bq.w};
#pragma unroll
        for (int i = 0; i < 4; i++)
#pragma unroll
            for (int j = 0; j < 4; j++)
                acc[i][j] = fmaf(ui[i], cj[j], fmaf(vi[i], qj[j], acc[i][j]));
    }

    float* qp = g_qp + (size_t)blockIdx.z * NB * NR;
#pragma unroll
    for (int i = 0; i < 4; i++) {
        float4 o = make_float4(acc[i][0], acc[i][1], acc[i][2], acc[i][3]);
        *(float4*)&qp[(bm0 + tm * 4 + i) * NR + bn0 + tn * 4] = o;
    }
}

// ---------------------------------------------------------------------------
// K23: one block per b, assoc row register-resident (read DRAM exactly once).
// Prologue: t0 (warp 0) -> s,h from qp partials (fused old k0/k1e).
// Phase 1: x[o] = sum_r s*assoc  (from registers)
// Phase A: coef[r] = h*dot(gx,assoc); new_assoc = assoc - lam_w*s*gx (regs)
// ---------------------------------------------------------------------------
__global__ __launch_bounds__(512) void k23(
    const float* __restrict__ assoc, const float* __restrict__ label,
    const float* __restrict__ z, const float* __restrict__ attn,
    float* __restrict__ out_x, float* __restrict__ out_assoc)
{
    __shared__ float ss[NR];
    __shared__ float hh[NR];
    __shared__ __align__(16) float red[32][NO];
    __shared__ __align__(16) float gx[NO];
    __shared__ __align__(16) float coef[NR];
    __shared__ float t0sh;

    int b = blockIdx.x;
    int tid = threadIdx.x;
    int o4 = tid & 15, rg = tid >> 4;

    const float4* ab4 = (const float4*)(assoc + (size_t)b * NR * NO);

    // Issue all 16 payload loads up-front (independent -> MLP 16/thread).
    float4 av[16];
#pragma unroll
    for (int i = 0; i < 16; i++)
        av[i] = __ldg(ab4 + (rg + 32 * i) * 16 + o4);

    // t0[b] = sum_d attn*z^2  (warp 0, hidden under payload load latency)
    if (tid < 32) {
        float4 zz = *(const float4*)&z[b * ND + tid * 4];
        float4 aa = *(const float4*)&attn[b * ND + tid * 4];
        float t = aa.x * zz.x * zz.x + aa.y * zz.y * zz.y
                + aa.z * zz.z * zz.z + aa.w * zz.w * zz.w;
#pragma unroll
        for (int off = 16; off; off >>= 1)
            t += __shfl_xor_sync(0xffffffffu, t, off);
        if (tid == 0) t0sh = t;
    }
    __syncthreads();

    // s,h from qp partials (fused k1e)
    {
        float q = g_qp[b * NR + tid] + g_qp[NB * NR + b * NR + tid] + t0sh;
        q = fmaxf(q, 1e-12f);
        float dd = sqrtf(q);
        float s = __expf(-BETA * dd);
        ss[tid] = s;
        hh[tid] = -0.5f * BETA * s / dd;
    }
    __syncthreads();

    // Phase 1: x reduction from registers
    {
        float4 acc = make_float4(0.f, 0.f, 0.f, 0.f);
#pragma unroll
        for (int i = 0; i < 16; i++) {
            float s = ss[rg + 32 * i];
            acc.x = fmaf(s, av[i].x, acc.x);
            acc.y = fmaf(s, av[i].y, acc.y);
            acc.z = fmaf(s, av[i].z, acc.z);
            acc.w = fmaf(s, av[i].w, acc.w);
        }
        *(float4*)&red[rg][o4 * 4] = acc;
    }
    __syncthreads();
    if (tid < NO) {
        float x = 0.f;
#pragma unroll
        for (int g2 = 0; g2 < 32; g2++) x += red[g2][tid];
        float l = label[b * NO + tid];
        float tmin = fminf(-1.f, x);
        float teacher = tmin - l * tmin + l * fmaxf(1.f, x);
        out_x[b * NO + tid] = 2.f * x;                 // PHI = 2
        gx[tid] = 0.03125f * (x - teacher);            // (2/O)*(x - teacher)
    }
    __syncthreads();

    // Phase A: coef + new_assoc from registers (zero re-read)
    {
        float4 g4 = *(const float4*)&gx[o4 * 4];
        float4* ob4 = (float4*)(out_assoc + (size_t)b * NR * NO);
#pragma unroll
        for (int i = 0; i < 16; i++) {
            int r = rg + 32 * i;
            float p = av[i].x * g4.x + av[i].y * g4.y
                    + av[i].z * g4.z + av[i].w * g4.w;
            float f = LAM_W * ss[r];
            float4 o;
            o.x = fmaf(-f, g4.x, av[i].x);
            o.y = fmaf(-f, g4.y, av[i].y);
            o.z = fmaf(-f, g4.z, av[i].z);
            o.w = fmaf(-f, g4.w, av[i].w);
            ob4[r * 16 + o4] = o;
            p += __shfl_xor_sync(0xffffffffu, p, 1);
            p += __shfl_xor_sync(0xffffffffu, p, 2);
            p += __shfl_xor_sync(0xffffffffu, p, 4);
            p += __shfl_xor_sync(0xffffffffu, p, 8);
            if (o4 == 0) coef[r] = hh[r] * p;
        }
    }
    __syncthreads();

    if (tid < NR / 4)
        ((float4*)&g_coef[b * NR])[tid] = ((const float4*)coef)[tid];
    if (tid < 32) {
        float p = 0.f;
#pragma unroll
        for (int i = 0; i < 16; i++) p += coef[tid + 32 * i];
#pragma unroll
        for (int off = 16; off; off >>= 1)
            p += __shfl_xor_sync(0xffffffffu, p, off);
        if (tid == 0) g_P[b] = p;
    }
}

// ---------------------------------------------------------------------------
// K4: dual GEMM partials  Q = coef @ C, S = coef @ C^2
// M=1024(b), N=128(d), K=512(r), split-R(4). 64x32 tile, 4x2x2 micro.
// grid (16, 4, 4) = 256 blocks, 256 threads, whole tile in smem.
// ---------------------------------------------------------------------------
#define K4_PAD 68
#define K4_SMEM_BYTES ((128 * K4_PAD + 2 * 128 * 32) * 4)   // 67584

__global__ __launch_bounds__(256, 3) void k4_gemm(const float* __restrict__ c)
{
    extern __shared__ __align__(16) float sm4[];
    float* Ac = sm4;                   // [r][m] coef
    float* Bc = Ac + 128 * K4_PAD;     // [r][n] c
    float* Bq = Bc + 128 * 32;         // [r][n] c^2

    int bm0 = blockIdx.x * 64;
    int bn0 = blockIdx.y * 32;
    int r0  = blockIdx.z * 128;
    int tid = threadIdx.x;

#pragma unroll
    for (int it = 0; it < 8; it++) {
        int i = tid + it * 256;
        int row = i >> 5, c4 = (i & 31) * 4;
        float4 a = *(const float4*)&g_coef[(bm0 + row) * NR + r0 + c4];
        Ac[(c4 + 0) * K4_PAD + row] = a.x;
        Ac[(c4 + 1) * K4_PAD + row] = a.y;
        Ac[(c4 + 2) * K4_PAD + row] = a.z;
        Ac[(c4 + 3) * K4_PAD + row] = a.w;
    }
#pragma unroll
    for (int it = 0; it < 4; it++) {
        int i = tid + it * 256;
        int row = i >> 3, c4 = (i & 7) * 4;
        float4 cc = *(const float4*)&c[(r0 + row) * ND + bn0 + c4];
        *(float4*)&Bc[row * 32 + c4] = cc;
        float4 q2 = make_float4(cc.x * cc.x, cc.y * cc.y, cc.z * cc.z, cc.w * cc.w);
        *(float4*)&Bq[row * 32 + c4] = q2;
    }
    __syncthreads();

    int tm = tid >> 4, tn = tid & 15;
    float aq[4][2] = {};
    float as_[4][2] = {};

#pragma unroll 8
    for (int kk = 0; kk < 128; kk++) {
        float4 a4 = *(const float4*)&Ac[kk * K4_PAD + tm * 4];
        float2 bc = *(const float2*)&Bc[kk * 32 + tn * 2];
        float2 bq = *(const float2*)&Bq[kk * 32 + tn * 2];
        float ai[4] = {a4.x, a4.y, a4.z, a4.w};
#pragma unroll
        for (int i = 0; i < 4; i++) {
            aq[i][0] = fmaf(ai[i], bc.x, aq[i][0]);
            aq[i][1] = fmaf(ai[i], bc.y, aq[i][1]);
            as_[i][0] = fmaf(ai[i], bq.x, as_[i][0]);
            as_[i][1] = fmaf(ai[i], bq.y, as_[i][1]);
        }
    }

    float* Qp = g_Qp + (size_t)blockIdx.z * NB * ND;
    float* Sp = g_Sp + (size_t)blockIdx.z * NB * ND;
#pragma unroll
    for (int i = 0; i < 4; i++) {
        int b = bm0 + tm * 4 + i;
        int k = bn0 + tn * 2;
        *(float2*)&Qp[b * ND + k] = make_float2(aq[i][0], aq[i][1]);
        *(float2*)&Sp[b * ND + k] = make_float2(as_[i][0], as_[i][1]);
    }
}

// ---------------------------------------------------------------------------
// K5: merge partials + new_attn = max(attn - lam_a*(z^2*P - 2z*Q + S), 0)
// ---------------------------------------------------------------------------
__global__ __launch_bounds__(256) void k5_attn(
    const float* __restrict__ z, const float* __restrict__ attn,
    float* __restrict__ out_attn)
{
    int idx = blockIdx.x * 256 + threadIdx.x;
    int b = idx >> 7;
    float Q = g_Qp[idx] + g_Qp[NB * ND + idx]
            + g_Qp[2 * NB * ND + idx] + g_Qp[3 * NB * ND + idx];
    float S = g_Sp[idx] + g_Sp[NB * ND + idx]
            + g_Sp[2 * NB * ND + idx] + g_Sp[3 * NB * ND + idx];
    float zz = z[idx];
    float P = g_P[b];
    float grad = fmaf(zz * zz, P, fmaf(-2.f * zz, Q, S));
    out_attn[idx] = fmaxf(fmaf(-LAM_A, grad, attn[idx]), 0.f);
}

// ---------------------------------------------------------------------------
extern "C" void kernel_launch(void* const* d_in, const int* in_sizes, int n_in,
                              void* d_out, int out_size)
{
    const float* z     = (const float*)d_in[0];  // (B,D)
    const float* label = (const float*)d_in[1];  // (B,O)
    const float* attn  = (const float*)d_in[2];  // (B,D)
    const float* assoc = (const float*)d_in[3];  // (B,R,O)
    const float* c     = (const float*)d_in[4];  // (R,D)

    float* out       = (float*)d_out;
    float* out_x     = out;                       // (B,O)
    float* out_attn  = out + NB * NO;             // (B,D)
    float* out_assoc = out + NB * NO + NB * ND;   // (B,R,O)

    static bool attr_done = false;
    if (!attr_done) {
        cudaFuncSetAttribute(k1_gemm, cudaFuncAttributeMaxDynamicSharedMemorySize,
                             K1_SMEM_BYTES);
        cudaFuncSetAttribute(k4_gemm, cudaFuncAttributeMaxDynamicSharedMemorySize,
                             K4_SMEM_BYTES);
        attr_done = true;
    }

    k1_gemm<<<dim3(NB / 64, NR / 64, 2), 256, K1_SMEM_BYTES>>>(z, attn, c);
    k23<<<NB, 512>>>(assoc, label, z, attn, out_x, out_assoc);
    k4_gemm<<<dim3(NB / 64, ND / 32, 4), 256, K4_SMEM_BYTES>>>(c);
    k5_attn<<<NB * ND / 256, 256>>>(z, attn, out_attn);
}